// round 9
// baseline (speedup 1.0000x reference)
#include <cuda_runtime.h>

// PV_LSTM on GB300 — round 3: 512-thread gate-split batch-parallel kernel.
// Block owns 16 batch rows. Thread (u, gp): u = tid&255 hidden unit,
// gp = tid>>8 gate pair (0 -> gates i,f ; 1 -> gates g,o).
// Packed fma.rn.f32x2 over 8 row-pairs; weights pre-interleaved so each
// thread does one coalesced LDG.128 per 2 k-values.

typedef unsigned long long u64;

#define HD 256
#define BATCH 16384
#define TB 16      // batch rows per block
#define NP 8       // f32x2 row-pairs
#define THREADS 512

// Scratch (allocation-free rule: __device__ globals).
// d_W2[l][gp<<17 | k2<<10 | u<<2 | c]:
//   c=0: Whh[(2gp+0)*256+u][2k2]   c=1: Whh[(2gp+1)*256+u][2k2]
//   c=2: Whh[(2gp+0)*256+u][2k2+1] c=3: Whh[(2gp+1)*256+u][2k2+1]
// d_Wih2[l][gp<<11 | s<<9 | u<<1 | g'] = Wih[(2gp+g')*256+u][s]
// d_b2[l][gp<<9 | u<<1 | g']          = bih+bhh for gate 2gp+g', unit u
__device__ __align__(16) float d_W2[4][HD * HD * 4];
__device__ __align__(16) float d_Wih2[4][4096];
__device__ __align__(16) float d_b2[4][1024];

struct WPtrs {
    const float* Wih[4];
    const float* Whh[4];
    const float* bih[4];
    const float* bhh[4];
};

struct HeadP {
    const float* fcsW; const float* fcsB;   // fc_speed   [4,256],[4]
    const float* fccW; const float* fccB;   // fc_cross   [2,256],[2]
    const float* embW; const float* embB;   // pos_emb    [4,256],[4]
    float* out;
};

// ---------------- packed / approx helpers ----------------
__device__ __forceinline__ u64 fma2(u64 a, u64 b, u64 c) {
    u64 d;
    asm("fma.rn.f32x2 %0, %1, %2, %3;" : "=l"(d) : "l"(a), "l"(b), "l"(c));
    return d;
}
__device__ __forceinline__ u64 bc2(float x) {
    u64 d;
    asm("mov.b64 %0, {%1, %1};" : "=l"(d) : "f"(x));
    return d;
}
__device__ __forceinline__ float2 up2(u64 v) {
    float2 r;
    asm("mov.b64 {%0, %1}, %2;" : "=f"(r.x), "=f"(r.y) : "l"(v));
    return r;
}
__device__ __forceinline__ float tanha(float x) {
    float y;
    asm("tanh.approx.f32 %0, %1;" : "=f"(y) : "f"(x));
    return y;
}
__device__ __forceinline__ float siga(float x) { return 0.5f * tanha(0.5f * x) + 0.5f; }
__device__ __forceinline__ float sigf(float x) { return 1.0f / (1.0f + __expf(-x)); }

// ---------------- weight prep (one launch) ----------------
__global__ void prep_kernel(WPtrs w) {
    int idx = blockIdx.x * 256 + threadIdx.x;
    const int NW = 4 * HD * HD * 4;   // 1048576
    const int NI = 4 * 4096;          // 16384
    const int NB = 4 * 1024;          // 4096
    if (idx < NW) {
        int l = idx >> 18;
        int rem = idx & 262143;
        int c   = rem & 3;
        int u   = (rem >> 2) & 255;
        int k2  = (rem >> 10) & 127;
        int gp  = rem >> 17;
        int g   = 2 * gp + (c & 1);
        int k   = 2 * k2 + (c >> 1);
        d_W2[l][rem] = w.Whh[l][(g * 256 + u) * 256 + k];
    } else if (idx < NW + NI) {
        int j = idx - NW;
        int l = j >> 12;
        int rem = j & 4095;
        int gpr = rem & 1;
        int u   = (rem >> 1) & 255;
        int s   = (rem >> 9) & 3;
        int gp  = rem >> 11;
        d_Wih2[l][rem] = w.Wih[l][((2 * gp + gpr) * 256 + u) * 4 + s];
    } else if (idx < NW + NI + NB) {
        int j = idx - NW - NI;
        int l = j >> 10;
        int rem = j & 1023;
        int gpr = rem & 1;
        int u   = (rem >> 1) & 255;
        int gp  = rem >> 9;
        int g   = 2 * gp + gpr;
        d_b2[l][rem] = w.bih[l][g * 256 + u] + w.bhh[l][g * 256 + u];
    }
}

// ---------------- one LSTM phase: 16 steps for this block's 16 rows ----------------
// mode: 0 encoder, 1 speed decoder, 2 crossing decoder.
// State (c2, hacc/cacc init/fin) is owned by gp==0 threads only.
__device__ __forceinline__ void run_phase(
    int l, int mode,
    const float* __restrict__ xseq,
    int tid, int b0,
    float* sh_h, float4* sh_go4, float* sh_x, const float* sh_hw,
    const float2* h_init, const float2* c_init,
    float2* h_fin, float2* c_fin,
    const HeadP& hp)
{
    const int u  = tid & 255;
    const int gp = tid >> 8;
    float2 c2[NP];

    if (gp == 0) {
        if (h_init) {
#pragma unroll
            for (int p = 0; p < NP; p++) {
                c2[p] = c_init[p];
                sh_h[u * 16 + 2 * p]     = h_init[p].x;
                sh_h[u * 16 + 2 * p + 1] = h_init[p].y;
            }
        } else {
#pragma unroll
            for (int p = 0; p < NP; p++) {
                c2[p] = make_float2(0.f, 0.f);
                sh_h[u * 16 + 2 * p]     = 0.f;
                sh_h[u * 16 + 2 * p + 1] = 0.f;
            }
        }
    }
    if (mode != 0 && tid < 64) {
        int r = tid >> 2, s = tid & 3;
        sh_x[s * 16 + r] = xseq[(size_t)(b0 + r) * 64 + 60 + s];
    }
    __syncthreads();

    for (int t = 0; t < 16; t++) {
        if (mode == 0) {
            if (tid < 64) {
                int r = tid >> 2, s = tid & 3;
                sh_x[s * 16 + r] = xseq[(size_t)(b0 + r) * 64 + t * 4 + s];
            }
            __syncthreads();
        }

        // ---- gate accumulators: bias + Wih*x (a0 = gate 2gp, a1 = gate 2gp+1) ----
        u64 a0[NP], a1[NP];
        {
            const float2 bb = *(const float2*)&d_b2[l][(gp * 256 + u) * 2];
            u64 b0v = bc2(bb.x), b1v = bc2(bb.y);
#pragma unroll
            for (int p = 0; p < NP; p++) { a0[p] = b0v; a1[p] = b1v; }
#pragma unroll
            for (int s = 0; s < 4; s++) {
                const float2 wv = *(const float2*)&d_Wih2[l][((gp * 4 + s) * 256 + u) * 2];
                u64 w0 = bc2(wv.x), w1 = bc2(wv.y);
                const u64* xp = (const u64*)(sh_x + s * 16);
#pragma unroll
                for (int p = 0; p < NP; p++) {
                    u64 x2 = xp[p];
                    a0[p] = fma2(w0, x2, a0[p]);
                    a1[p] = fma2(w1, x2, a1[p]);
                }
            }
        }

        // ---- main recurrence: + Whh*h ----
        const float* wl = d_W2[l] + (gp << 17);
#pragma unroll 8
        for (int k2 = 0; k2 < 128; k2++) {
            const float4 w = *(const float4*)&wl[((k2 << 8) + u) << 2];
            u64 w0e = bc2(w.x), w1e = bc2(w.y), w0o = bc2(w.z), w1o = bc2(w.w);
            const u64* he = (const u64*)(sh_h + (k2 << 5));
            const u64* ho = he + 8;
#pragma unroll
            for (int p = 0; p < NP; p++) {
                u64 h2 = he[p];
                a0[p] = fma2(w0e, h2, a0[p]);
                a1[p] = fma2(w1e, h2, a1[p]);
            }
#pragma unroll
            for (int p = 0; p < NP; p++) {
                u64 h2 = ho[p];
                a0[p] = fma2(w0o, h2, a0[p]);
                a1[p] = fma2(w1o, h2, a1[p]);
            }
        }

        // ---- gate exchange + cell update ----
        if (gp == 1) {
            // a0 = g-gate raw, a1 = o-gate raw -> send tanh(g), sig(o)
#pragma unroll
            for (int p = 0; p < NP; p++) {
                float2 g = up2(a0[p]), o = up2(a1[p]);
                float4 v;
                v.x = tanha(g.x); v.y = tanha(g.y);
                v.z = siga(o.x);  v.w = siga(o.y);
                sh_go4[u * 8 + ((p + u) & 7)] = v;
            }
        }
        __syncthreads();   // go visible; all old-h reads done
        if (gp == 0) {
#pragma unroll
            for (int p = 0; p < NP; p++) {
                float4 go = sh_go4[u * 8 + ((p + u) & 7)];
                float2 vi = up2(a0[p]), vf = up2(a1[p]);
                c2[p].x = siga(vf.x) * c2[p].x + siga(vi.x) * go.x;
                c2[p].y = siga(vf.y) * c2[p].y + siga(vi.y) * go.y;
                float hx = go.z * tanha(c2[p].x);
                float hy = go.w * tanha(c2[p].y);
                sh_h[u * 16 + 2 * p]     = hx;
                sh_h[u * 16 + 2 * p + 1] = hy;
            }
        }
        __syncthreads();   // new h visible

        // ---- decoder heads ----
        if (mode == 1) {
            if (tid < 64) {
                int r = tid >> 2, s = tid & 3;
                float acc = hp.fcsB[s];
                const float* wr = sh_hw + s * 256;
#pragma unroll 8
                for (int k = 0; k < HD; k++) acc += sh_h[k * 16 + r] * wr[k];
                float v = fminf(fmaxf(acc, -100.f), 100.f);   // hardtanh(100)
                hp.out[(size_t)(b0 + r) * 64 + t * 4 + s] = v;
                sh_x[s * 16 + r] = v;                          // feedback
            }
            __syncthreads();
        } else if (mode == 2) {
            if (tid < 64) {
                int r = tid >> 2, s = tid & 3;
                float acc = hp.embB[s];
                const float* wr = sh_hw + 1536 + s * 256;
#pragma unroll 8
                for (int k = 0; k < HD; k++) acc += sh_h[k * 16 + r] * wr[k];
                sh_x[s * 16 + r] = fmaxf(acc, 0.f);            // relu(emb) feedback
            } else if (tid >= 64 && tid < 80) {
                int r = tid - 64;
                float l0 = hp.fccB[0], l1 = hp.fccB[1];
                const float* w0 = sh_hw + 1024;
                const float* w1 = sh_hw + 1280;
#pragma unroll 8
                for (int k = 0; k < HD; k++) {
                    float hv = sh_h[k * 16 + r];
                    l0 += hv * w0[k];
                    l1 += hv * w1[k];
                }
                l0 = fmaxf(l0, 0.f);
                l1 = fmaxf(l1, 0.f);
                float m = fmaxf(l0, l1);
                float e0 = __expf(l0 - m), e1 = __expf(l1 - m);
                float inv = 1.0f / (e0 + e1);
                size_t base = (size_t)BATCH * 64 + (size_t)(b0 + r) * 32 + (size_t)t * 2;
                hp.out[base]     = e0 * inv;
                hp.out[base + 1] = e1 * inv;
            }
            __syncthreads();
        }
    }

    // accumulate final state (encoders): h0 = hsp + hpo, c0 = csp + cpo
    if (gp == 0 && h_fin) {
#pragma unroll
        for (int p = 0; p < NP; p++) {
            h_fin[p].x += sh_h[u * 16 + 2 * p];
            h_fin[p].y += sh_h[u * 16 + 2 * p + 1];
            c_fin[p].x += c2[p].x;
            c_fin[p].y += c2[p].y;
        }
    }
}

// ---------------- whole network, one launch ----------------
// Dynamic smem layout (floats):
//   [0, 4096)          sh_h   h[k][r]                     16 KB
//   [4096, 12288)      sh_go  float4[2048] (g,o exchange) 32 KB
//   [12288, 12352)     sh_x   x[s][r]
//   [12352, 14912)     sh_hw  fcsW | fccW | embW          10 KB
__global__ void __launch_bounds__(THREADS, 1) pv_main(
    HeadP hp, const float* __restrict__ speed, const float* __restrict__ pos)
{
    extern __shared__ __align__(16) float smem[];
    float*  sh_h   = smem;
    float4* sh_go4 = (float4*)(smem + 4096);
    float*  sh_x   = smem + 12288;
    float*  sh_hw  = smem + 12352;

    const int tid = threadIdx.x;
    const int b0 = blockIdx.x * TB;

    // stage head weights
    for (int i = tid; i < 1024; i += THREADS) sh_hw[i] = hp.fcsW[i];
    for (int i = tid; i < 512;  i += THREADS) sh_hw[1024 + i] = hp.fccW[i];
    for (int i = tid; i < 1024; i += THREADS) sh_hw[1536 + i] = hp.embW[i];

    float2 hacc[NP], cacc[NP];
#pragma unroll
    for (int p = 0; p < NP; p++) {
        hacc[p] = make_float2(0.f, 0.f);
        cacc[p] = make_float2(0.f, 0.f);
    }

    // encoders (accumulate summed final state)
    run_phase(0, 0, speed, tid, b0, sh_h, sh_go4, sh_x, sh_hw, nullptr, nullptr, hacc, cacc, hp);
    run_phase(1, 0, pos,   tid, b0, sh_h, sh_go4, sh_x, sh_hw, nullptr, nullptr, hacc, cacc, hp);
    // decoders (both start from (h0, c0))
    run_phase(2, 1, speed, tid, b0, sh_h, sh_go4, sh_x, sh_hw, hacc, cacc, nullptr, nullptr, hp);
    run_phase(3, 2, pos,   tid, b0, sh_h, sh_go4, sh_x, sh_hw, hacc, cacc, nullptr, nullptr, hp);
}

extern "C" void kernel_launch(void* const* d_in, const int* in_sizes, int n_in,
                              void* d_out, int out_size) {
    (void)in_sizes; (void)n_in; (void)out_size;

    WPtrs w;
    // LSTM order: 0=sp_enc, 1=po_enc, 2=dec_speed, 3=dec_cross
    const int base[4] = {2, 6, 10, 14};
    for (int l = 0; l < 4; l++) {
        w.Wih[l] = (const float*)d_in[base[l] + 0];
        w.Whh[l] = (const float*)d_in[base[l] + 1];
        w.bih[l] = (const float*)d_in[base[l] + 2];
        w.bhh[l] = (const float*)d_in[base[l] + 3];
    }

    HeadP hp;
    hp.fcsW = (const float*)d_in[18];
    hp.fcsB = (const float*)d_in[19];
    hp.fccW = (const float*)d_in[20];
    hp.fccB = (const float*)d_in[21];
    hp.embW = (const float*)d_in[22];
    hp.embB = (const float*)d_in[23];
    hp.out  = (float*)d_out;

    const float* speed = (const float*)d_in[0];
    const float* pos   = (const float*)d_in[1];

    const int SMEM_BYTES = 14912 * 4;   // 59648
    cudaFuncSetAttribute(pv_main, cudaFuncAttributeMaxDynamicSharedMemorySize, SMEM_BYTES);

    // (1048576 + 16384 + 4096) / 256 = 4176 blocks
    prep_kernel<<<4176, 256>>>(w);
    pv_main<<<BATCH / TB, THREADS, SMEM_BYTES>>>(hp, speed, pos);
}

// round 14
// speedup vs baseline: 3.0697x; 3.0697x over previous
#include <cuda_runtime.h>
#include <cuda_fp16.h>
#include <cstdint>

typedef unsigned int u32;

#define BATCH 16384
#define LDA 280                    // fp16 elems per A row (272 used, padded)
#define LDB 280
#define TILEB (64 * LDB * 2)       // 35840 bytes per B tile

// ---------------- device scratch (allocation-free rule) ----------------
__device__ __align__(16) __half d_Bw[4][16][64 * LDB];   // [layer][ntile][n][k]
__device__ float d_hs[(size_t)BATCH * 256];
__device__ float d_cs[(size_t)BATCH * 256];

struct Params {
    const float* Wih[4]; const float* Whh[4];
    const float* bih[4]; const float* bhh[4];
    const float* fcsW; const float* fcsB;
    const float* fccW; const float* fccB;
    const float* embW; const float* embB;
    const float* speed; const float* pos;
    float* out;
};

// ---------------- PTX helpers (all legal on compute_103) ----------------
__device__ __forceinline__ u32 s2u(const void* p) {
    u32 a;
    asm("{ .reg .u64 t; cvta.to.shared.u64 t, %1; cvt.u32.u64 %0, t; }" : "=r"(a) : "l"(p));
    return a;
}
__device__ __forceinline__ void ldsm4(u32* r, u32 a) {
    asm volatile("ldmatrix.sync.aligned.m8n8.x4.shared.b16 {%0,%1,%2,%3}, [%4];"
                 : "=r"(r[0]), "=r"(r[1]), "=r"(r[2]), "=r"(r[3]) : "r"(a));
}
__device__ __forceinline__ void mma16816(float* c, const u32* a, const u32* b) {
    asm volatile("mma.sync.aligned.m16n8k16.row.col.f32.f16.f16.f32 "
                 "{%0,%1,%2,%3}, {%4,%5,%6,%7}, {%8,%9}, {%0,%1,%2,%3};"
                 : "+f"(c[0]), "+f"(c[1]), "+f"(c[2]), "+f"(c[3])
                 : "r"(a[0]), "r"(a[1]), "r"(a[2]), "r"(a[3]), "r"(b[0]), "r"(b[1]));
}
__device__ __forceinline__ void cp16(u32 dst, const void* src) {
    asm volatile("cp.async.cg.shared.global [%0], [%1], 16;" :: "r"(dst), "l"(src) : "memory");
}
#define CP_COMMIT() asm volatile("cp.async.commit_group;" ::: "memory")
#define CP_WAIT(n)  asm volatile("cp.async.wait_group %0;" :: "n"(n) : "memory")

__device__ __forceinline__ float tanha(float x) {
    float y; asm("tanh.approx.f32 %0, %1;" : "=f"(y) : "f"(x)); return y;
}
__device__ __forceinline__ float sigm(float x) { return fmaf(tanha(0.5f * x), 0.5f, 0.5f); }

// ---------------- prep: pack fp16 B tiles [n = 4u+g][k] ----------------
// k: 0-255 Whh, 256-259 Wih, 260 bias(ih+hh), 261-279 zero.
__global__ void prep_kernel(Params P) {
    int idx = blockIdx.x * 256 + threadIdx.x;   // one thread = 8 k values
    if (idx >= 4 * 16 * 64 * 35) return;
    int kc = idx % 35, nl = (idx / 35) & 63, nt = (idx / (35 * 64)) & 15, l = idx / (35 * 64 * 16);
    int g = nl & 3, ul = nl >> 2, u = nt * 16 + ul, row = g * 256 + u;
    int k0 = kc * 8;
    __half hv[8];
#pragma unroll
    for (int i = 0; i < 8; i++) {
        int k = k0 + i; float v = 0.f;
        if (k < 256)       v = P.Whh[l][(size_t)row * 256 + k];
        else if (k < 260)  v = P.Wih[l][row * 4 + (k - 256)];
        else if (k == 260) v = P.bih[l][row] + P.bhh[l][row];
        hv[i] = __float2half(v);
    }
    *(uint4*)(&d_Bw[l][nt][nl * LDB + k0]) = *(uint4*)hv;
}

// ---------------- one LSTM phase (16 steps, 64 rows) ----------------
// mode: 0 enc-store, 1 enc-add, 2 dec-speed, 3 dec-cross
__device__ void run_phase(int mode, const __half* __restrict__ Bl,
                          const float* __restrict__ xseq, float* __restrict__ out,
                          int b0, int tid,
                          __half* A0, __half* A1, u32 a0u, u32 a1u,
                          u32 bs, float* shc, const float* shw, const float* sb,
                          float* lg)
{
    const int lane = tid & 31, w = tid >> 5;
    const int m = w >> 2, p = w & 3;
    const int R0 = 32 * m;
    const int q = lane >> 2, cc = lane & 3;
    const int hrow = tid >> 2, hs = tid & 3;            // x-writer mapping

    // ---- phase init ----
    if (mode <= 1) {
        for (int i = tid; i < 64 * 256; i += 256) {
            int u = i & 255, r = i >> 8;
            A0[r * LDA + u] = __float2half(0.f);
            shc[u * 65 + r] = 0.f;
        }
    } else {
        for (int i = tid; i < 64 * 256; i += 256) {
            int u = i & 255, r = i >> 8;
            size_t gidx = (size_t)(b0 + r) * 256 + u;
            A0[r * LDA + u] = __float2half(d_hs[gidx]);
            shc[u * 65 + r] = d_cs[gidx];
        }
        A0[hrow * LDA + 256 + hs] = __float2half(xseq[(size_t)(b0 + hrow) * 64 + 60 + hs]);
    }
    __syncthreads();

    for (int t = 0; t < 16; t++) {
        __half* Ac = (t & 1) ? A1 : A0;
        __half* An = (t & 1) ? A0 : A1;
        u32 acu = (t & 1) ? a1u : a0u;

        if (mode <= 1) {   // encoder: fresh x
            Ac[hrow * LDA + 256 + hs] = __float2half(xseq[(size_t)(b0 + hrow) * 64 + t * 4 + hs]);
            __syncthreads();
        }

        // prefetch tiles 0,1
        for (int pt = 0; pt < 2; pt++) {
            const char* src = (const char*)(Bl + pt * 64 * LDB);
            for (u32 o = (u32)tid * 16u; o < TILEB; o += 4096u) cp16(bs + pt * TILEB + o, src + o);
            CP_COMMIT();
        }

        // ---- 16 N-tiles of 64 gates ----
        for (int nt = 0; nt < 16; nt++) {
            if (nt == 15) { CP_WAIT(0); } else { CP_WAIT(1); }
            __syncthreads();

            float acc[2][2][4];
#pragma unroll
            for (int i = 0; i < 2; i++)
#pragma unroll
                for (int j = 0; j < 2; j++)
#pragma unroll
                    for (int e = 0; e < 4; e++) acc[i][j][e] = 0.f;

            const u32 bslot = bs + (nt & 1) * TILEB;
            // lane-fixed address components
            const u32 aoff0 = acu + (u32)((R0 + (lane & 15)) * LDA + (lane >> 4) * 8) * 2u;
            const int nr = 16 * p + (lane & 7) + ((lane >> 4) & 1) * 8;
            const u32 boff = bslot + (u32)(nr * LDB + ((lane >> 3) & 1) * 8) * 2u;

#pragma unroll
            for (int kt = 0; kt < 17; kt++) {
                u32 aF0[4], aF1[4], bF[4];
                ldsm4(bF, boff + kt * 32u);               // B: [n][k] col-major K×N -> NO trans
                ldsm4(aF0, aoff0 + kt * 32u);
                ldsm4(aF1, aoff0 + kt * 32u + (u32)(16 * LDA * 2));
                mma16816(acc[0][0], aF0, bF);
                mma16816(acc[0][1], aF0, bF + 2);
                mma16816(acc[1][0], aF1, bF);
                mma16816(acc[1][1], aF1, bF + 2);
            }

            // ---- epilogue: gate exchange + cell update ----
#pragma unroll
            for (int mi = 0; mi < 2; mi++)
#pragma unroll
                for (int fj = 0; fj < 2; fj++) {
                    float p0 = __shfl_xor_sync(0xFFFFFFFFu, acc[mi][fj][0], 1);
                    float p1 = __shfl_xor_sync(0xFFFFFFFFu, acc[mi][fj][1], 1);
                    float p2 = __shfl_xor_sync(0xFFFFFFFFu, acc[mi][fj][2], 1);
                    float p3 = __shfl_xor_sync(0xFFFFFFFFu, acc[mi][fj][3], 1);
                    if ((cc & 1) == 0) {
                        int u = nt * 16 + 4 * p + 2 * fj + (cc >> 1);
                        int r = R0 + 16 * mi + q;
                        float c0 = shc[u * 65 + r];
                        float cn = sigm(acc[mi][fj][1]) * c0 + sigm(acc[mi][fj][0]) * tanha(p0);
                        shc[u * 65 + r] = cn;
                        An[r * LDA + u] = __float2half(sigm(p1) * tanha(cn));
                        int r8 = r + 8;
                        float c1 = shc[u * 65 + r8];
                        float cn1 = sigm(acc[mi][fj][3]) * c1 + sigm(acc[mi][fj][2]) * tanha(p2);
                        shc[u * 65 + r8] = cn1;
                        An[r8 * LDA + u] = __float2half(sigm(p3) * tanha(cn1));
                    }
                }
            __syncthreads();
            if (nt + 2 < 16) {
                const char* src = (const char*)(Bl + (nt + 2) * 64 * LDB);
                for (u32 o = (u32)tid * 16u; o < TILEB; o += 4096u)
                    cp16(bs + (nt & 1) * TILEB + o, src + o);
                CP_COMMIT();
            }
        }

        // ---- decoder heads (h complete in An) ----
        if (mode >= 2) {
            const __half2* a2 = (const __half2*)(An + hrow * LDA);
            int widx = (mode == 2) ? hs : (hs + 4);
            const float* wr = shw + widx * 256;
            float acc0 = 0.f, acc1 = 0.f;
#pragma unroll 8
            for (int k = 0; k < 128; k++) {
                float2 f = __half22float2(a2[k]);
                acc0 = fmaf(f.x, wr[2 * k], acc0);
                acc1 = fmaf(f.y, wr[2 * k + 1], acc1);
            }
            float dv = acc0 + acc1 + sb[widx];
            if (mode == 2) {
                float v = fminf(fmaxf(dv, -100.f), 100.f);
                out[(size_t)(b0 + hrow) * 64 + t * 4 + hs] = v;
                An[hrow * LDA + 256 + hs] = __float2half(v);
            } else {
                An[hrow * LDA + 256 + hs] = __float2half(fmaxf(dv, 0.f));
                if (hs < 2) {
                    const float* wc = shw + (8 + hs) * 256;
                    float b0a = 0.f, b1a = 0.f;
#pragma unroll 8
                    for (int k = 0; k < 128; k++) {
                        float2 f = __half22float2(a2[k]);
                        b0a = fmaf(f.x, wc[2 * k], b0a);
                        b1a = fmaf(f.y, wc[2 * k + 1], b1a);
                    }
                    lg[hrow * 2 + hs] = fmaxf(b0a + b1a + sb[8 + hs], 0.f);
                }
            }
            __syncthreads();
            if (mode == 3 && hs == 0) {
                float l0 = lg[hrow * 2], l1 = lg[hrow * 2 + 1];
                float mx = fmaxf(l0, l1);
                float e0 = __expf(l0 - mx), e1 = __expf(l1 - mx);
                float inv = 1.0f / (e0 + e1);
                float2 cv = make_float2(e0 * inv, e1 * inv);
                *(float2*)(out + (size_t)BATCH * 64 + (size_t)(b0 + hrow) * 32 + t * 2) = cv;
            }
            __syncthreads();
        }
    }

    // ---- encoder tail: stash final h (in A0 after 16 steps) + c ----
    if (mode <= 1) {
        for (int i = tid; i < 64 * 256; i += 256) {
            int u = i & 255, r = i >> 8;
            float h = __half2float(A0[r * LDA + u]);
            float cv = shc[u * 65 + r];
            size_t gidx = (size_t)(b0 + r) * 256 + u;
            if (mode == 0) { d_hs[gidx] = h; d_cs[gidx] = cv; }
            else           { d_hs[gidx] += h; d_cs[gidx] += cv; }
        }
        __syncthreads();
    }
}

// ---------------- main kernel ----------------
// smem (bytes): bs0 0 | bs1 35840 | A0 71680 | A1 107520 | c 143360(+66560)
//               shw 209920(+10240) | sb 220160(+64) | lg 220224(+512)
__global__ void __launch_bounds__(256, 1) pv_main(Params P) {
    extern __shared__ __align__(16) char sm[];
    const u32 base = s2u(sm);
    const int tid = threadIdx.x;
    const int b0 = blockIdx.x * 64;

    u32 bs = base;
    __half* A0 = (__half*)(sm + 71680);
    __half* A1 = (__half*)(sm + 107520);
    u32 a0u = base + 71680, a1u = base + 107520;
    float* shc = (float*)(sm + 143360);
    float* shw = (float*)(sm + 209920);
    float* sb  = (float*)(sm + 220160);
    float* lg  = (float*)(sm + 220224);

    // zero A buffers fully (pads), set bias col 260 = 1.0
    for (int i = tid; i < 64 * LDA; i += 256) {
        A0[i] = __float2half(0.f);
        A1[i] = __float2half(0.f);
    }
    // head weights: rows 0-3 fcs, 4-7 emb, 8-9 fcc
    for (int i = tid; i < 2560; i += 256) {
        int r = i >> 8, k = i & 255;
        float v = (r < 4) ? P.fcsW[r * 256 + k] : (r < 8) ? P.embW[(r - 4) * 256 + k]
                : P.fccW[(r - 8) * 256 + k];
        shw[i] = v;
    }
    if (tid < 4) sb[tid] = P.fcsB[tid];
    else if (tid < 8) sb[tid] = P.embB[tid - 4];
    else if (tid < 10) sb[tid] = P.fccB[tid - 8];
    __syncthreads();
    if (tid < 64) {
        A0[tid * LDA + 260] = __float2half(1.f);
        A1[tid * LDA + 260] = __float2half(1.f);
    }
    __syncthreads();

    run_phase(0, d_Bw[0][0], P.speed, P.out, b0, tid, A0, A1, a0u, a1u, bs, shc, shw, sb, lg);
    run_phase(1, d_Bw[1][0], P.pos,   P.out, b0, tid, A0, A1, a0u, a1u, bs, shc, shw, sb, lg);
    run_phase(2, d_Bw[2][0], P.speed, P.out, b0, tid, A0, A1, a0u, a1u, bs, shc, shw, sb, lg);
    run_phase(3, d_Bw[3][0], P.pos,   P.out, b0, tid, A0, A1, a0u, a1u, bs, shc, shw, sb, lg);
}

extern "C" void kernel_launch(void* const* d_in, const int* in_sizes, int n_in,
                              void* d_out, int out_size) {
    (void)in_sizes; (void)n_in; (void)out_size;

    Params P;
    P.speed = (const float*)d_in[0];
    P.pos   = (const float*)d_in[1];
    const int base[4] = {2, 6, 10, 14};   // sp_enc, po_enc, dec_speed, dec_cross
    for (int l = 0; l < 4; l++) {
        P.Wih[l] = (const float*)d_in[base[l] + 0];
        P.Whh[l] = (const float*)d_in[base[l] + 1];
        P.bih[l] = (const float*)d_in[base[l] + 2];
        P.bhh[l] = (const float*)d_in[base[l] + 3];
    }
    P.fcsW = (const float*)d_in[18]; P.fcsB = (const float*)d_in[19];
    P.fccW = (const float*)d_in[20]; P.fccB = (const float*)d_in[21];
    P.embW = (const float*)d_in[22]; P.embB = (const float*)d_in[23];
    P.out  = (float*)d_out;

    const int SMEM = 220800;
    cudaFuncSetAttribute(pv_main, cudaFuncAttributeMaxDynamicSharedMemorySize, SMEM);

    prep_kernel<<<560, 256>>>(P);             // 143360 chunks
    pv_main<<<BATCH / 64, 256, SMEM>>>(P);
}

// round 15
// speedup vs baseline: 3.6812x; 1.1992x over previous
#include <cuda_runtime.h>
#include <cuda_fp16.h>
#include <cstdint>

typedef unsigned int u32;

#define BATCH 16384
#define LDA 280                    // fp16 elems per A row (272 used, padded)
#define LDB 280
#define TILEB (64 * LDB * 2)       // 35840 bytes per B tile
#define THREADS 512

// ---------------- device scratch (allocation-free rule) ----------------
__device__ __align__(16) __half d_Bw[4][16][64 * LDB];   // [layer][ntile][n][k]
__device__ float d_hs[(size_t)BATCH * 256];
__device__ float d_cs[(size_t)BATCH * 256];

struct Params {
    const float* Wih[4]; const float* Whh[4];
    const float* bih[4]; const float* bhh[4];
    const float* fcsW; const float* fcsB;
    const float* fccW; const float* fccB;
    const float* embW; const float* embB;
    const float* speed; const float* pos;
    float* out;
};

// ---------------- PTX helpers (all legal on compute_103) ----------------
__device__ __forceinline__ u32 s2u(const void* p) {
    u32 a;
    asm("{ .reg .u64 t; cvta.to.shared.u64 t, %1; cvt.u32.u64 %0, t; }" : "=r"(a) : "l"(p));
    return a;
}
__device__ __forceinline__ void ldsm4(u32* r, u32 a) {
    asm volatile("ldmatrix.sync.aligned.m8n8.x4.shared.b16 {%0,%1,%2,%3}, [%4];"
                 : "=r"(r[0]), "=r"(r[1]), "=r"(r[2]), "=r"(r[3]) : "r"(a));
}
__device__ __forceinline__ void mma16816(float* c, const u32* a, const u32* b) {
    asm volatile("mma.sync.aligned.m16n8k16.row.col.f32.f16.f16.f32 "
                 "{%0,%1,%2,%3}, {%4,%5,%6,%7}, {%8,%9}, {%0,%1,%2,%3};"
                 : "+f"(c[0]), "+f"(c[1]), "+f"(c[2]), "+f"(c[3])
                 : "r"(a[0]), "r"(a[1]), "r"(a[2]), "r"(a[3]), "r"(b[0]), "r"(b[1]));
}
__device__ __forceinline__ void cp16(u32 dst, const void* src) {
    asm volatile("cp.async.cg.shared.global [%0], [%1], 16;" :: "r"(dst), "l"(src) : "memory");
}
#define CP_COMMIT() asm volatile("cp.async.commit_group;" ::: "memory")
#define CP_WAIT(n)  asm volatile("cp.async.wait_group %0;" :: "n"(n) : "memory")

__device__ __forceinline__ float tanha(float x) {
    float y; asm("tanh.approx.f32 %0, %1;" : "=f"(y) : "f"(x)); return y;
}
__device__ __forceinline__ float sigm(float x) { return fmaf(tanha(0.5f * x), 0.5f, 0.5f); }

// ---------------- prep: pack fp16 B tiles [n = 4u+g][k] ----------------
// k: 0-255 Whh, 256-259 Wih, 260 bias(ih+hh), 261-279 zero.
__global__ void prep_kernel(Params P) {
    int idx = blockIdx.x * 256 + threadIdx.x;   // one thread = 8 k values
    if (idx >= 4 * 16 * 64 * 35) return;
    int kc = idx % 35, nl = (idx / 35) & 63, nt = (idx / (35 * 64)) & 15, l = idx / (35 * 64 * 16);
    int g = nl & 3, ul = nl >> 2, u = nt * 16 + ul, row = g * 256 + u;
    int k0 = kc * 8;
    __half hv[8];
#pragma unroll
    for (int i = 0; i < 8; i++) {
        int k = k0 + i; float v = 0.f;
        if (k < 256)       v = P.Whh[l][(size_t)row * 256 + k];
        else if (k < 260)  v = P.Wih[l][row * 4 + (k - 256)];
        else if (k == 260) v = P.bih[l][row] + P.bhh[l][row];
        hv[i] = __float2half(v);
    }
    *(uint4*)(&d_Bw[l][nt][nl * LDB + k0]) = *(uint4*)hv;
}

// ---------------- one LSTM phase (16 steps, 64 rows) ----------------
// mode: 0 enc-store, 1 enc-add, 2 dec-speed, 3 dec-cross
__device__ void run_phase(int mode, const __half* __restrict__ Bl,
                          const float* __restrict__ xseq, float* __restrict__ out,
                          int b0, int tid,
                          __half* A0, __half* A1, u32 a0u, u32 a1u,
                          u32 bs, float* shc, const float* shw, const float* sb,
                          float* lg)
{
    const int lane = tid & 31, w = tid >> 5;
    const int m = w >> 2, p = w & 3;          // 4 m-groups x 4 n-groups
    const int R0 = 16 * m;
    const int q = lane >> 2, cc = lane & 3;
    const int hrow = (tid & 255) >> 2, hs = tid & 3;   // x/head mapping (tid<256 active)

    // ---- phase init ----
    if (mode <= 1) {
        for (int i = tid; i < 64 * 256; i += THREADS) {
            int u = i & 255, r = i >> 8;
            A0[r * LDA + u] = __float2half(0.f);
            shc[u * 65 + r] = 0.f;
        }
    } else {
        for (int i = tid; i < 64 * 256; i += THREADS) {
            int u = i & 255, r = i >> 8;
            size_t gidx = (size_t)(b0 + r) * 256 + u;
            A0[r * LDA + u] = __float2half(d_hs[gidx]);
            shc[u * 65 + r] = d_cs[gidx];
        }
        if (tid < 256)
            A0[hrow * LDA + 256 + hs] = __float2half(xseq[(size_t)(b0 + hrow) * 64 + 60 + hs]);
    }
    __syncthreads();

    for (int t = 0; t < 16; t++) {
        __half* Ac = (t & 1) ? A1 : A0;
        __half* An = (t & 1) ? A0 : A1;
        u32 acu = (t & 1) ? a1u : a0u;

        if (mode <= 1) {   // encoder: fresh x
            if (tid < 256)
                Ac[hrow * LDA + 256 + hs] = __float2half(xseq[(size_t)(b0 + hrow) * 64 + t * 4 + hs]);
            __syncthreads();
        }

        // ---- hoist A fragments for this step (16 rows x 272 k) ----
        u32 aF[17][4];
        {
            const u32 aoff = acu + (u32)((R0 + (lane & 15)) * LDA + (lane >> 4) * 8) * 2u;
#pragma unroll
            for (int kt = 0; kt < 17; kt++) ldsm4(aF[kt], aoff + kt * 32u);
        }

        // prefetch tiles 0,1
        for (int pt = 0; pt < 2; pt++) {
            const char* src = (const char*)(Bl + pt * 64 * LDB);
            for (u32 o = (u32)tid * 16u; o < TILEB; o += (u32)THREADS * 16u)
                cp16(bs + pt * TILEB + o, src + o);
            CP_COMMIT();
        }

        // ---- 16 N-tiles of 64 gates ----
        for (int nt = 0; nt < 16; nt++) {
            if (nt == 15) { CP_WAIT(0); } else { CP_WAIT(1); }
            __syncthreads();

            float acc[2][4];
#pragma unroll
            for (int j = 0; j < 2; j++)
#pragma unroll
                for (int e = 0; e < 4; e++) acc[j][e] = 0.f;

            const u32 bslot = bs + (nt & 1) * TILEB;
            const int nr = 16 * p + (lane & 7) + ((lane >> 4) & 1) * 8;
            const u32 boff = bslot + (u32)(nr * LDB + ((lane >> 3) & 1) * 8) * 2u;

#pragma unroll
            for (int kt = 0; kt < 17; kt++) {
                u32 bF[4];
                ldsm4(bF, boff + kt * 32u);            // B: [n][k] = col-major KxN, NO trans
                mma16816(acc[0], aF[kt], bF);
                mma16816(acc[1], aF[kt], bF + 2);
            }

            // ---- epilogue: gate exchange + cell update ----
#pragma unroll
            for (int fj = 0; fj < 2; fj++) {
                float p0 = __shfl_xor_sync(0xFFFFFFFFu, acc[fj][0], 1);
                float p1 = __shfl_xor_sync(0xFFFFFFFFu, acc[fj][1], 1);
                float p2 = __shfl_xor_sync(0xFFFFFFFFu, acc[fj][2], 1);
                float p3 = __shfl_xor_sync(0xFFFFFFFFu, acc[fj][3], 1);
                if ((cc & 1) == 0) {
                    int u = nt * 16 + 4 * p + 2 * fj + (cc >> 1);
                    int r = R0 + q;
                    float c0 = shc[u * 65 + r];
                    float cn = sigm(acc[fj][1]) * c0 + sigm(acc[fj][0]) * tanha(p0);
                    shc[u * 65 + r] = cn;
                    An[r * LDA + u] = __float2half(sigm(p1) * tanha(cn));
                    int r8 = r + 8;
                    float c1 = shc[u * 65 + r8];
                    float cn1 = sigm(acc[fj][3]) * c1 + sigm(acc[fj][2]) * tanha(p2);
                    shc[u * 65 + r8] = cn1;
                    An[r8 * LDA + u] = __float2half(sigm(p3) * tanha(cn1));
                }
            }
            __syncthreads();
            if (nt + 2 < 16) {
                const char* src = (const char*)(Bl + (nt + 2) * 64 * LDB);
                for (u32 o = (u32)tid * 16u; o < TILEB; o += (u32)THREADS * 16u)
                    cp16(bs + (nt & 1) * TILEB + o, src + o);
                CP_COMMIT();
            }
        }

        // ---- decoder heads (h complete in An) ----
        if (mode >= 2) {
            if (tid < 256) {
                const __half2* a2 = (const __half2*)(An + hrow * LDA);
                int widx = (mode == 2) ? hs : (hs + 4);
                const float* wr = shw + widx * 256;
                float acc0 = 0.f, acc1 = 0.f;
#pragma unroll 8
                for (int k = 0; k < 128; k++) {
                    float2 f = __half22float2(a2[k]);
                    acc0 = fmaf(f.x, wr[2 * k], acc0);
                    acc1 = fmaf(f.y, wr[2 * k + 1], acc1);
                }
                float dv = acc0 + acc1 + sb[widx];
                if (mode == 2) {
                    float v = fminf(fmaxf(dv, -100.f), 100.f);
                    out[(size_t)(b0 + hrow) * 64 + t * 4 + hs] = v;
                    An[hrow * LDA + 256 + hs] = __float2half(v);
                } else {
                    An[hrow * LDA + 256 + hs] = __float2half(fmaxf(dv, 0.f));
                    if (hs < 2) {
                        const float* wc = shw + (8 + hs) * 256;
                        float b0a = 0.f, b1a = 0.f;
#pragma unroll 8
                        for (int k = 0; k < 128; k++) {
                            float2 f = __half22float2(a2[k]);
                            b0a = fmaf(f.x, wc[2 * k], b0a);
                            b1a = fmaf(f.y, wc[2 * k + 1], b1a);
                        }
                        lg[hrow * 2 + hs] = fmaxf(b0a + b1a + sb[8 + hs], 0.f);
                    }
                }
            }
            __syncthreads();
            if (mode == 3 && tid < 256 && hs == 0) {
                float l0 = lg[hrow * 2], l1 = lg[hrow * 2 + 1];
                float mx = fmaxf(l0, l1);
                float e0 = __expf(l0 - mx), e1 = __expf(l1 - mx);
                float inv = 1.0f / (e0 + e1);
                float2 cv = make_float2(e0 * inv, e1 * inv);
                *(float2*)(out + (size_t)BATCH * 64 + (size_t)(b0 + hrow) * 32 + t * 2) = cv;
            }
            __syncthreads();
        }
    }

    // ---- encoder tail: stash final h (in A0 after 16 steps) + c ----
    if (mode <= 1) {
        for (int i = tid; i < 64 * 256; i += THREADS) {
            int u = i & 255, r = i >> 8;
            float h = __half2float(A0[r * LDA + u]);
            float cv = shc[u * 65 + r];
            size_t gidx = (size_t)(b0 + r) * 256 + u;
            if (mode == 0) { d_hs[gidx] = h; d_cs[gidx] = cv; }
            else           { d_hs[gidx] += h; d_cs[gidx] += cv; }
        }
        __syncthreads();
    }
}

// ---------------- main kernel ----------------
// smem (bytes): bs0 0 | bs1 35840 | A0 71680 | A1 107520 | c 143360(+66560)
//               shw 209920(+10240) | sb 220160(+64) | lg 220224(+512)
__global__ void __launch_bounds__(THREADS, 1) pv_main(Params P) {
    extern __shared__ __align__(16) char sm[];
    const u32 base = s2u(sm);
    const int tid = threadIdx.x;
    const int b0 = blockIdx.x * 64;

    u32 bs = base;
    __half* A0 = (__half*)(sm + 71680);
    __half* A1 = (__half*)(sm + 107520);
    u32 a0u = base + 71680, a1u = base + 107520;
    float* shc = (float*)(sm + 143360);
    float* shw = (float*)(sm + 209920);
    float* sb  = (float*)(sm + 220160);
    float* lg  = (float*)(sm + 220224);

    // zero A buffers fully (pads), set bias col 260 = 1.0
    for (int i = tid; i < 64 * LDA; i += THREADS) {
        A0[i] = __float2half(0.f);
        A1[i] = __float2half(0.f);
    }
    // head weights: rows 0-3 fcs, 4-7 emb, 8-9 fcc
    for (int i = tid; i < 2560; i += THREADS) {
        int r = i >> 8, k = i & 255;
        float v = (r < 4) ? P.fcsW[r * 256 + k] : (r < 8) ? P.embW[(r - 4) * 256 + k]
                : P.fccW[(r - 8) * 256 + k];
        shw[i] = v;
    }
    if (tid < 4) sb[tid] = P.fcsB[tid];
    else if (tid < 8) sb[tid] = P.embB[tid - 4];
    else if (tid < 10) sb[tid] = P.fccB[tid - 8];
    __syncthreads();
    if (tid < 64) {
        A0[tid * LDA + 260] = __float2half(1.f);
        A1[tid * LDA + 260] = __float2half(1.f);
    }
    __syncthreads();

    run_phase(0, d_Bw[0][0], P.speed, P.out, b0, tid, A0, A1, a0u, a1u, bs, shc, shw, sb, lg);
    run_phase(1, d_Bw[1][0], P.pos,   P.out, b0, tid, A0, A1, a0u, a1u, bs, shc, shw, sb, lg);
    run_phase(2, d_Bw[2][0], P.speed, P.out, b0, tid, A0, A1, a0u, a1u, bs, shc, shw, sb, lg);
    run_phase(3, d_Bw[3][0], P.pos,   P.out, b0, tid, A0, A1, a0u, a1u, bs, shc, shw, sb, lg);
}

extern "C" void kernel_launch(void* const* d_in, const int* in_sizes, int n_in,
                              void* d_out, int out_size) {
    (void)in_sizes; (void)n_in; (void)out_size;

    Params P;
    P.speed = (const float*)d_in[0];
    P.pos   = (const float*)d_in[1];
    const int base[4] = {2, 6, 10, 14};   // sp_enc, po_enc, dec_speed, dec_cross
    for (int l = 0; l < 4; l++) {
        P.Wih[l] = (const float*)d_in[base[l] + 0];
        P.Whh[l] = (const float*)d_in[base[l] + 1];
        P.bih[l] = (const float*)d_in[base[l] + 2];
        P.bhh[l] = (const float*)d_in[base[l] + 3];
    }
    P.fcsW = (const float*)d_in[18]; P.fcsB = (const float*)d_in[19];
    P.fccW = (const float*)d_in[20]; P.fccB = (const float*)d_in[21];
    P.embW = (const float*)d_in[22]; P.embB = (const float*)d_in[23];
    P.out  = (float*)d_out;

    const int SMEM = 220800;
    cudaFuncSetAttribute(pv_main, cudaFuncAttributeMaxDynamicSharedMemorySize, SMEM);

    prep_kernel<<<560, 256>>>(P);             // 143360 chunks
    pv_main<<<BATCH / 64, THREADS, SMEM>>>(P);
}